// round 6
// baseline (speedup 1.0000x reference)
#include <cuda_runtime.h>
#include <cuda_fp16.h>
#include <math.h>
#include <cstdint>

// ---------------------------------------------------------------------------
// Problem constants: B=8, L=2048, D=1024, K=32, J=512
//   backbone0 n=2050, summarize n=514, backbone1 n=2082
//   Pad to NP=2176 (17*128) and NS=640 (5*128).
// ---------------------------------------------------------------------------
#define Bn 8
#define Dn 1024
#define NP 2176
#define NS 640

#define EL_XD ((size_t)Bn * NP * Dn)
#define EL_PP ((size_t)Bn * NP * NP)

__device__ __align__(256) __half g_X[EL_XD];
__device__ __align__(256) __half g_Q[EL_XD];
__device__ __align__(256) __half g_K[EL_XD];
__device__ __align__(256) __half g_Vt[EL_XD];   // V transposed [d][token]
__device__ __align__(256) __half g_O[EL_XD];
__device__ __align__(256) __half g_P[EL_PP];
__device__ __align__(256) float  g_S[EL_PP];
__device__ __align__(256) float  g_H[EL_XD];
__device__ __align__(256) __half g_WqT[Dn*Dn], g_WkT[Dn*Dn], g_WvT[Dn*Dn], g_WoT[Dn*Dn];
// stage C fp32 scratch
__device__ __align__(256) float g_M1[128 * Dn];
__device__ __align__(256) float g_S1[128 * Dn];
__device__ __align__(256) float g_Qn[128 * Dn];
__device__ __align__(256) float g_Kp[128 * Dn];
__device__ __align__(256) float g_P1[Bn * Dn];

// ---------------------------------------------------------------------------
// helpers
// ---------------------------------------------------------------------------
__device__ __forceinline__ uint32_t smem_u32(const void* p) {
    uint32_t a;
    asm("{ .reg .u64 t; cvta.to.shared.u64 t, %1; cvt.u32.u64 %0, t; }"
        : "=r"(a) : "l"(p));
    return a;
}
// SW128 swizzle for [row][64 half] tiles (128B rows): 16B chunk col XOR row%8
__device__ __forceinline__ uint32_t swz(int row, int col16) {
    return ((uint32_t)row << 7) | ((uint32_t)((col16 ^ row) & 7) << 4);
}
__device__ __forceinline__ void ldsm4(uint32_t* r, uint32_t addr) {
    asm volatile("ldmatrix.sync.aligned.m8n8.x4.shared.b16 {%0,%1,%2,%3}, [%4];"
        : "=r"(r[0]), "=r"(r[1]), "=r"(r[2]), "=r"(r[3]) : "r"(addr));
}
__device__ __forceinline__ void mma_f16(float* d, const uint32_t* a, const uint32_t* b) {
    asm volatile(
        "mma.sync.aligned.m16n8k16.row.col.f32.f16.f16.f32 "
        "{%0,%1,%2,%3}, {%4,%5,%6,%7}, {%8,%9}, {%0,%1,%2,%3};"
        : "+f"(d[0]), "+f"(d[1]), "+f"(d[2]), "+f"(d[3])
        : "r"(a[0]), "r"(a[1]), "r"(a[2]), "r"(a[3]), "r"(b[0]), "r"(b[1]));
}

// Register fragment set for one 16-K step of a 64x32 warp tile
struct Frag {
    uint32_t A[4][4];
    uint32_t B[2][4];
};
__device__ __forceinline__ void load_frags(Frag& f, uint32_t aA, uint32_t aB,
                                           int kk, int m0, int n0, int lane)
{
    const int k16 = kk << 1;
    const int ar = m0 + (lane & 15);
    const int ac = k16 + (lane >> 4);
#pragma unroll
    for (int i = 0; i < 4; i++)
        ldsm4(f.A[i], aA + swz(ar + 16 * i, ac));
    const int br = n0 + ((lane >> 4) << 3) + (lane & 7);
    const int bc = k16 + ((lane >> 3) & 1);
#pragma unroll
    for (int j2 = 0; j2 < 2; j2++)
        ldsm4(f.B[j2], aB + swz(br + 16 * j2, bc));
}

// ---------------------------------------------------------------------------
// fp16 tensor-core GEMM: C = scale * A * B^T (+bias over cols)
//   A: [M][Kd] K-major fp16; B: [N][Kd] K-major fp16.
//   CTA tile 128x128, warp tile 64x32 (8 warps 2x4), K-chunk 64,
//   3-stage cp.async smem ring + double-buffered register fragments
//   (ldsm for step kk+1 issued before the mmas of step kk).
//   MODE 0: fp32 out; MODE 1: fp16 out; MODE 2: fp16 TRANSPOSED out.
//   Batched via blockIdx.z (element strides sA, sB, sC).
// ---------------------------------------------------------------------------
#define STAGE_B 32768            // A tile 16KB + B tile 16KB
#define TG_SMEM (3 * STAGE_B)    // 98304 bytes

__device__ __forceinline__ void fill_chunk(uint32_t sm,
    const __half* A, const __half* Bm, int Kd, int t, int c)
{
    long long k0 = (long long)c << 6;
#pragma unroll
    for (int i = 0; i < 4; i++) {
        int seg = t + (i << 8);          // 0..1023 = row*8 + chunk
        int row = seg >> 3;
        int cc  = seg & 7;
        uint32_t so = swz(row, cc);
        long long go = (long long)row * Kd + k0 + ((long long)cc << 3);
        asm volatile("cp.async.cg.shared.global [%0], [%1], 16;"
                     :: "r"(sm + so), "l"(A + go));
        asm volatile("cp.async.cg.shared.global [%0], [%1], 16;"
                     :: "r"(sm + 16384u + so), "l"(Bm + go));
    }
}

template <int MODE, bool BIAS>
__global__ void __launch_bounds__(256)
tgemm(const __half* __restrict__ A, const __half* __restrict__ Bm,
      float* __restrict__ Cf, __half* __restrict__ Ch,
      const float* __restrict__ bias,
      int Kd, int ldc, float scale,
      long long sA, long long sB, long long sC)
{
    extern __shared__ __align__(1024) char smem[];
    const int tid = threadIdx.x, wid = tid >> 5, lane = tid & 31;
    const long long z = blockIdx.z;
    A += z * sA; Bm += z * sB;
    if (MODE == 0) Cf += z * sC; else Ch += z * sC;

    const uint32_t sb = smem_u32(smem);
    const __half* At = A  + (long long)blockIdx.y * 128 * Kd;
    const __half* Bt = Bm + (long long)blockIdx.x * 128 * Kd;

    const int wr = wid >> 2, wc = wid & 3;    // 2 x 4 warp grid
    const int m0 = wr * 64, n0 = wc * 32;

    float acc[4][4][4];
#pragma unroll
    for (int i = 0; i < 4; i++)
#pragma unroll
        for (int j = 0; j < 4; j++)
#pragma unroll
            for (int r = 0; r < 4; r++) acc[i][j][r] = 0.f;

    const int NC = Kd >> 6;
    fill_chunk(sb, At, Bt, Kd, tid, 0);
    asm volatile("cp.async.commit_group;");
    if (NC > 1) {
        fill_chunk(sb + STAGE_B, At, Bt, Kd, tid, 1);
        asm volatile("cp.async.commit_group;");
    }

    Frag fb[2];

#pragma unroll 1
    for (int c = 0; c < NC; c++) {
        if (c == NC - 1) asm volatile("cp.async.wait_group 0;");
        else             asm volatile("cp.async.wait_group 1;");
        __syncthreads();

        const uint32_t tb = sb + (uint32_t)(c % 3) * STAGE_B;
        const uint32_t aA = tb, aB = tb + 16384u;

        // prime fragment pipeline for this chunk
        load_frags(fb[0], aA, aB, 0, m0, n0, lane);

#pragma unroll
        for (int kk = 0; kk < 4; kk++) {
            const int cur = kk & 1;
            if (kk < 3)
                load_frags(fb[cur ^ 1], aA, aB, kk + 1, m0, n0, lane);
#pragma unroll
            for (int i = 0; i < 4; i++)
#pragma unroll
                for (int jt = 0; jt < 4; jt++)
                    mma_f16(acc[i][jt], fb[cur].A[i],
                            &fb[cur].B[jt >> 1][(jt & 1) << 1]);
        }
        if (c + 2 < NC) {
            fill_chunk(sb + (uint32_t)((c + 2) % 3) * STAGE_B, At, Bt, Kd, tid, c + 2);
            asm volatile("cp.async.commit_group;");
        }
    }

    // ---------------- epilogue ----------------
    const int row0 = blockIdx.y * 128, col0 = blockIdx.x * 128;
    const int rl = lane >> 2;              // 0..7
    const int cl = (lane & 3) << 1;        // 0,2,4,6
#pragma unroll
    for (int i = 0; i < 4; i++) {
        const long long rg0 = row0 + m0 + i * 16 + rl;
        const long long rg1 = rg0 + 8;
#pragma unroll
        for (int j = 0; j < 4; j++) {
            const int cg = col0 + n0 + j * 8 + cl;
            float v00 = acc[i][j][0] * scale, v01 = acc[i][j][1] * scale;
            float v10 = acc[i][j][2] * scale, v11 = acc[i][j][3] * scale;
            if (BIAS) {
                const float b0 = bias[cg], b1 = bias[cg + 1];
                v00 += b0; v01 += b1; v10 += b0; v11 += b1;
            }
            if (MODE == 0) {
                *(float2*)(Cf + rg0 * ldc + cg) = make_float2(v00, v01);
                *(float2*)(Cf + rg1 * ldc + cg) = make_float2(v10, v11);
            } else if (MODE == 1) {
                *(__half2*)(Ch + rg0 * ldc + cg) =
                    __halves2half2(__float2half_rn(v00), __float2half_rn(v01));
                *(__half2*)(Ch + rg1 * ldc + cg) =
                    __halves2half2(__float2half_rn(v10), __float2half_rn(v11));
            } else {
                Ch[(long long)cg * ldc + rg0]       = __float2half_rn(v00);
                Ch[(long long)(cg + 1) * ldc + rg0] = __float2half_rn(v01);
                Ch[(long long)cg * ldc + rg1]       = __float2half_rn(v10);
                Ch[(long long)(cg + 1) * ldc + rg1] = __float2half_rn(v11);
            }
        }
    }
}

// ---------------------------------------------------------------------------
// Row softmax over fp32 scores -> fp16 probabilities (pad keys zeroed)
// ---------------------------------------------------------------------------
__global__ void softmax_h(const float* __restrict__ S, __half* __restrict__ P,
                          int n, int npad)
{
    const long long roff = ((long long)blockIdx.y * npad + blockIdx.x) * npad;
    const float* row = S + roff;
    __half* pr = P + roff;
    const int t = threadIdx.x;
    __shared__ float red[256];

    float m = -1e30f;
    for (int j = t; j < n; j += 256) m = fmaxf(m, row[j]);
    red[t] = m; __syncthreads();
    for (int s = 128; s > 0; s >>= 1) {
        if (t < s) red[t] = fmaxf(red[t], red[t + s]);
        __syncthreads();
    }
    m = red[0]; __syncthreads();

    float sum = 0.f;
    for (int j = t; j < n; j += 256) sum += __expf(row[j] - m);
    red[t] = sum; __syncthreads();
    for (int s = 128; s > 0; s >>= 1) {
        if (t < s) red[t] += red[t + s];
        __syncthreads();
    }
    const float inv = 1.f / red[0];

    for (int j = t; j < npad; j += 256) {
        float p = (j < n) ? __expf(row[j] - m) * inv : 0.f;
        pr[j] = __float2half_rn(p);
    }
}

// ---------------------------------------------------------------------------
// Input assembly (fp32 -> fp16)
// ---------------------------------------------------------------------------
__global__ void build_x0h(const float* __restrict__ seg0, __half* __restrict__ X)
{
    int b = blockIdx.y;
    long long i = (long long)blockIdx.x * 256 + threadIdx.x;
    int pos = (int)(i >> 10), d = (int)(i & 1023);
    float v = 0.f;
    if (pos >= 1 && pos <= 2048)
        v = seg0[((long long)b * 2048 + (pos - 1)) * 1024 + d];
    X[(long long)b * NP * 1024 + i] = __float2half_rn(v);
}

__global__ void build_xsh(const float* __restrict__ seg1, const float* __restrict__ pe,
                          __half* __restrict__ X)
{
    int b = blockIdx.y;
    long long i = (long long)blockIdx.x * 256 + threadIdx.x;
    int pos = (int)(i >> 10), d = (int)(i & 1023);
    float v = 0.f;
    if (pos == 0 || pos == 513) v = pe[d];
    else if (pos >= 1 && pos <= 512)
        v = seg1[((long long)b * 2048 + (pos - 1)) * 1024 + d];
    X[(long long)b * NS * 1024 + i] = __float2half_rn(v);
}

__global__ void build_x1h(const float* __restrict__ seg0, const float* __restrict__ seg1,
                          const float* __restrict__ P1, __half* __restrict__ X)
{
    int b = blockIdx.y;
    long long i = (long long)blockIdx.x * 256 + threadIdx.x;
    int pos = (int)(i >> 10), d = (int)(i & 1023);
    float v = 0.f;
    if (pos < 32)
        v = seg0[((long long)b * 2048 + (2016 + pos)) * 1024 + d];
    else if (pos == 32 || pos == 2081)
        v = P1[b * 1024 + d];
    else if (pos >= 33 && pos <= 2080)
        v = seg1[((long long)b * 2048 + (pos - 33)) * 1024 + d];
    X[(long long)b * NP * 1024 + i] = __float2half_rn(v);
}

// weight transpose + convert: WT[n][k] = half(W[k][n])
__global__ void wcvt_t(const float* __restrict__ W, __half* __restrict__ WT)
{
    long long i = (long long)blockIdx.x * 256 + threadIdx.x;  // i = k*1024+n
    int k = (int)(i >> 10), n = (int)(i & 1023);
    WT[(long long)n * 1024 + k] = __float2half_rn(W[i]);
}

__global__ void copy_out(const float* __restrict__ H, float* __restrict__ out,
                         int tokens, int npad, long long off)
{
    int b = blockIdx.y;
    long long i = (long long)blockIdx.x * 256 + threadIdx.x;
    out[off + (long long)b * tokens * 1024 + i] =
        H[(long long)b * npad * 1024 + (long long)33 * 1024 + i];
}

__global__ void copy_pad128(const float* __restrict__ H, float* __restrict__ dst,
                            int npad, int token)
{
    long long i = (long long)blockIdx.x * 256 + threadIdx.x;
    int r = (int)(i >> 10), d = (int)(i & 1023);
    dst[i] = (r < Bn) ? H[((long long)r * npad + token) * 1024 + d] : 0.f;
}

// ---------------------------------------------------------------------------
// fp32 fallback SGEMM (stage C only; tiny)
// ---------------------------------------------------------------------------
template <bool TRANSB, bool BIAS>
__global__ void __launch_bounds__(256)
sgemm(const float* __restrict__ A, const float* __restrict__ Bm,
      float* __restrict__ C, const float* __restrict__ bias,
      int N, int Kd, float scale)
{
    __shared__ float As[8][128];
    __shared__ float Bs[8][128];
    const int t = threadIdx.x, tx = t & 15, ty = t >> 4;
    const int row0 = blockIdx.y * 128, col0 = blockIdx.x * 128;
    const int aRow = t >> 1, aCol = (t & 1) << 2;
    const int bRow = t >> 5, bCol = (t & 31) << 2;
    float acc[8][8];
#pragma unroll
    for (int i = 0; i < 8; i++)
#pragma unroll
        for (int j = 0; j < 8; j++) acc[i][j] = 0.f;
    const float* Aptr = A + (long long)(row0 + aRow) * Kd + aCol;
    const float* Bptr = TRANSB ? (Bm + (long long)(col0 + aRow) * Kd + aCol)
                               : (Bm + (long long)bRow * N + col0 + bCol);
    for (int k0 = 0; k0 < Kd; k0 += 8) {
        float4 av = *(const float4*)(Aptr + k0);
        As[aCol + 0][aRow] = av.x; As[aCol + 1][aRow] = av.y;
        As[aCol + 2][aRow] = av.z; As[aCol + 3][aRow] = av.w;
        if (TRANSB) {
            float4 bv = *(const float4*)(Bptr + k0);
            Bs[aCol + 0][aRow] = bv.x; Bs[aCol + 1][aRow] = bv.y;
            Bs[aCol + 2][aRow] = bv.z; Bs[aCol + 3][aRow] = bv.w;
        } else {
            float4 bv = *(const float4*)(Bptr + (long long)k0 * N);
            *(float4*)&Bs[bRow][bCol] = bv;
        }
        __syncthreads();
#pragma unroll
        for (int kk = 0; kk < 8; kk++) {
            float ar[8], br[8];
            *(float4*)&ar[0] = *(const float4*)&As[kk][ty * 8];
            *(float4*)&ar[4] = *(const float4*)&As[kk][ty * 8 + 4];
            *(float4*)&br[0] = *(const float4*)&Bs[kk][tx * 8];
            *(float4*)&br[4] = *(const float4*)&Bs[kk][tx * 8 + 4];
#pragma unroll
            for (int i = 0; i < 8; i++)
#pragma unroll
                for (int j = 0; j < 8; j++)
                    acc[i][j] = fmaf(ar[i], br[j], acc[i][j]);
        }
        __syncthreads();
    }
#pragma unroll
    for (int i = 0; i < 8; i++) {
        long long r = row0 + ty * 8 + i;
#pragma unroll
        for (int j = 0; j < 8; j += 4) {
            int c = col0 + tx * 8 + j;
            float4 v;
            v.x = acc[i][j + 0] * scale; v.y = acc[i][j + 1] * scale;
            v.z = acc[i][j + 2] * scale; v.w = acc[i][j + 3] * scale;
            if (BIAS) { v.x += bias[c]; v.y += bias[c + 1]; v.z += bias[c + 2]; v.w += bias[c + 3]; }
            *(float4*)(C + r * N + c) = v;
        }
    }
}

// Tiny 8-way memory attention
__global__ void mem_attn(const float* __restrict__ Qn, const float* __restrict__ Kp,
                         const float* __restrict__ M1, float* __restrict__ P1)
{
    int b = blockIdx.x, t = threadIdx.x;
    __shared__ float red[256];
    __shared__ float attn[Bn];
    for (int j = 0; j < Bn; j++) {
        float p = 0.f;
        for (int d = t; d < 1024; d += 256)
            p += Qn[b * 1024 + d] * Kp[j * 1024 + d];
        red[t] = p; __syncthreads();
        for (int s = 128; s > 0; s >>= 1) {
            if (t < s) red[t] += red[t + s];
            __syncthreads();
        }
        if (t == 0) attn[j] = red[0] * 0.03125f;
        __syncthreads();
    }
    if (t == 0) {
        float m = -1e30f;
        for (int j = 0; j < Bn; j++) m = fmaxf(m, attn[j]);
        float s = 0.f;
        for (int j = 0; j < Bn; j++) { attn[j] = __expf(attn[j] - m); s += attn[j]; }
        float inv = 1.f / s;
        for (int j = 0; j < Bn; j++) attn[j] *= inv;
    }
    __syncthreads();
    for (int d = t; d < 1024; d += 256) {
        float v = 0.f;
#pragma unroll
        for (int j = 0; j < Bn; j++) v += attn[j] * M1[j * 1024 + d];
        P1[b * 1024 + d] = v;
    }
}

// ---------------------------------------------------------------------------
// Host orchestration
// ---------------------------------------------------------------------------
struct Ptrs {
    __half *X, *Q, *K, *Vt, *O, *P;
    __half *WqT, *WkT, *WvT, *WoT;
    float *S, *H, *M1, *S1, *Qn, *Kp, *P1;
};

static void run_backbone_tc(const Ptrs& p,
                            const float* bq, const float* bk,
                            const float* bv, const float* bo,
                            int n, int npad)
{
    const int mt = npad / 128;
    const long long sXD = (long long)npad * Dn;
    const long long sPP = (long long)npad * npad;
    dim3 gp(Dn / 128, mt, Bn);
    // projections
    tgemm<1, true><<<gp, 256, TG_SMEM>>>(p.X, p.WqT, nullptr, p.Q, bq,
                                         Dn, Dn, 1.f, sXD, 0, sXD);
    tgemm<1, true><<<gp, 256, TG_SMEM>>>(p.X, p.WkT, nullptr, p.K, bk,
                                         Dn, Dn, 1.f, sXD, 0, sXD);
    tgemm<2, true><<<gp, 256, TG_SMEM>>>(p.X, p.WvT, nullptr, p.Vt, bv,
                                         Dn, npad, 1.f, sXD, 0, sXD);
    // scores
    dim3 gs(mt, mt, Bn);
    tgemm<0, false><<<gs, 256, TG_SMEM>>>(p.Q, p.K, p.S, nullptr, nullptr,
                                          Dn, npad, 0.03125f, sXD, sXD, sPP);
    softmax_h<<<dim3(n, Bn), 256>>>(p.S, p.P, n, npad);
    // attn @ V
    tgemm<1, false><<<gp, 256, TG_SMEM>>>(p.P, p.Vt, nullptr, p.O, nullptr,
                                          npad, Dn, 1.f, sPP, sXD, sXD);
    // output proj
    tgemm<0, true><<<gp, 256, TG_SMEM>>>(p.O, p.WoT, p.H, nullptr, bo,
                                         Dn, Dn, 1.f, sXD, 0, sXD);
}

extern "C" void kernel_launch(void* const* d_in, const int* in_sizes, int n_in,
                              void* d_out, int out_size)
{
    const float* seg0   = (const float*)d_in[0];
    const float* seg1   = (const float*)d_in[1];
    const float* pe     = (const float*)d_in[2];
    const float* Wq_mem = (const float*)d_in[3];
    const float* bq_mem = (const float*)d_in[4];
    const float* Wk_mem = (const float*)d_in[5];
    const float* bk_mem = (const float*)d_in[6];
    const float* Wq     = (const float*)d_in[7];
    const float* bq     = (const float*)d_in[8];
    const float* Wk     = (const float*)d_in[9];
    const float* bk     = (const float*)d_in[10];
    const float* Wv     = (const float*)d_in[11];
    const float* bv     = (const float*)d_in[12];
    const float* Wo     = (const float*)d_in[13];
    const float* bo     = (const float*)d_in[14];
    float* out = (float*)d_out;

    cudaFuncSetAttribute(tgemm<0, false>, cudaFuncAttributeMaxDynamicSharedMemorySize, TG_SMEM);
    cudaFuncSetAttribute(tgemm<0, true>,  cudaFuncAttributeMaxDynamicSharedMemorySize, TG_SMEM);
    cudaFuncSetAttribute(tgemm<1, false>, cudaFuncAttributeMaxDynamicSharedMemorySize, TG_SMEM);
    cudaFuncSetAttribute(tgemm<1, true>,  cudaFuncAttributeMaxDynamicSharedMemorySize, TG_SMEM);
    cudaFuncSetAttribute(tgemm<2, true>,  cudaFuncAttributeMaxDynamicSharedMemorySize, TG_SMEM);

    Ptrs p;
    cudaGetSymbolAddress((void**)&p.X, g_X);
    cudaGetSymbolAddress((void**)&p.Q, g_Q);
    cudaGetSymbolAddress((void**)&p.K, g_K);
    cudaGetSymbolAddress((void**)&p.Vt, g_Vt);
    cudaGetSymbolAddress((void**)&p.O, g_O);
    cudaGetSymbolAddress((void**)&p.P, g_P);
    cudaGetSymbolAddress((void**)&p.WqT, g_WqT);
    cudaGetSymbolAddress((void**)&p.WkT, g_WkT);
    cudaGetSymbolAddress((void**)&p.WvT, g_WvT);
    cudaGetSymbolAddress((void**)&p.WoT, g_WoT);
    cudaGetSymbolAddress((void**)&p.S, g_S);
    cudaGetSymbolAddress((void**)&p.H, g_H);
    cudaGetSymbolAddress((void**)&p.M1, g_M1);
    cudaGetSymbolAddress((void**)&p.S1, g_S1);
    cudaGetSymbolAddress((void**)&p.Qn, g_Qn);
    cudaGetSymbolAddress((void**)&p.Kp, g_Kp);
    cudaGetSymbolAddress((void**)&p.P1, g_P1);

    const int WG = Dn * Dn / 256;
    wcvt_t<<<WG, 256>>>(Wq, p.WqT);
    wcvt_t<<<WG, 256>>>(Wk, p.WkT);
    wcvt_t<<<WG, 256>>>(Wv, p.WvT);
    wcvt_t<<<WG, 256>>>(Wo, p.WoT);

    // ---- Stage A: backbone over input_h0 (n = 2050) ----
    build_x0h<<<dim3(NP * Dn / 256, Bn), 256>>>(seg0, p.X);
    run_backbone_tc(p, bq, bk, bv, bo, 2050, NP);
    copy_out<<<dim3(2016 * Dn / 256, Bn), 256>>>(p.H, out, 2016, NP, 0LL);
    copy_pad128<<<dim3(128 * Dn / 256), 256>>>(p.H, p.M1, NP, 2049);

    // ---- Stage B: summarize(seg1) (n = 514) ----
    build_xsh<<<dim3(NS * Dn / 256, Bn), 256>>>(seg1, pe, p.X);
    run_backbone_tc(p, bq, bk, bv, bo, 514, NS);
    copy_pad128<<<dim3(128 * Dn / 256), 256>>>(p.H, p.S1, NS, 512);

    // ---- Stage C: memory attention (tiny, fp32 path) ----
    dim3 gMem(Dn / 128, 1, 1);
    sgemm<false, true><<<gMem, 256>>>(p.S1, Wq_mem, p.Qn, bq_mem, Dn, Dn, 1.f);
    sgemm<false, true><<<gMem, 256>>>(p.M1, Wk_mem, p.Kp, bk_mem, Dn, Dn, 1.f);
    mem_attn<<<Bn, 256>>>(p.Qn, p.Kp, p.M1, p.P1);

    // ---- Stage D: backbone over input_h1 (n = 2082) ----
    build_x1h<<<dim3(NP * Dn / 256, Bn), 256>>>(seg0, seg1, p.P1, p.X);
    run_backbone_tc(p, bq, bk, bv, bo, 2082, NP);
    copy_out<<<dim3(2048 * Dn / 256, Bn), 256>>>(p.H, out, 2048, NP,
                                                 (long long)Bn * 2016 * Dn);
}

// round 7
// speedup vs baseline: 1.0781x; 1.0781x over previous
#include <cuda_runtime.h>
#include <cuda_fp16.h>
#include <math.h>
#include <cstdint>

// ---------------------------------------------------------------------------
// Problem constants: B=8, L=2048, D=1024, K=32, J=512
//   backbone0 n=2050, summarize n=514, backbone1 n=2082
//   Pad to NP=2176 (17*128) and NS=640 (5*128).
// ---------------------------------------------------------------------------
#define Bn 8
#define Dn 1024
#define NP 2176
#define NS 640

#define EL_XD ((size_t)Bn * NP * Dn)
#define EL_PP ((size_t)Bn * NP * NP)

__device__ __align__(256) __half g_X[EL_XD];
__device__ __align__(256) __half g_Q[EL_XD];
__device__ __align__(256) __half g_K[EL_XD];
__device__ __align__(256) __half g_Vt[EL_XD];   // V transposed [d][token]
__device__ __align__(256) __half g_O[EL_XD];
__device__ __align__(256) __half g_P[EL_PP];
__device__ __align__(256) float  g_S[EL_PP];
__device__ __align__(256) float  g_H[EL_XD];
__device__ __align__(256) __half g_WqT[Dn*Dn], g_WkT[Dn*Dn], g_WvT[Dn*Dn], g_WoT[Dn*Dn];
// stage C fp32 scratch
__device__ __align__(256) float g_M1[128 * Dn];
__device__ __align__(256) float g_S1[128 * Dn];
__device__ __align__(256) float g_Qn[128 * Dn];
__device__ __align__(256) float g_Kp[128 * Dn];
__device__ __align__(256) float g_P1[Bn * Dn];

// ---------------------------------------------------------------------------
// helpers
// ---------------------------------------------------------------------------
__device__ __forceinline__ uint32_t smem_u32(const void* p) {
    uint32_t a;
    asm("{ .reg .u64 t; cvta.to.shared.u64 t, %1; cvt.u32.u64 %0, t; }"
        : "=r"(a) : "l"(p));
    return a;
}
// SW128 swizzle for [row][64 half] tiles (128B rows): 16B chunk col XOR row%8
__device__ __forceinline__ uint32_t swz(int row, int col16) {
    return ((uint32_t)row << 7) | ((uint32_t)((col16 ^ row) & 7) << 4);
}
__device__ __forceinline__ void ldsm4(uint32_t* r, uint32_t addr) {
    asm volatile("ldmatrix.sync.aligned.m8n8.x4.shared.b16 {%0,%1,%2,%3}, [%4];"
        : "=r"(r[0]), "=r"(r[1]), "=r"(r[2]), "=r"(r[3]) : "r"(addr));
}
__device__ __forceinline__ void mma_f16(float* d, const uint32_t* a, const uint32_t* b) {
    asm volatile(
        "mma.sync.aligned.m16n8k16.row.col.f32.f16.f16.f32 "
        "{%0,%1,%2,%3}, {%4,%5,%6,%7}, {%8,%9}, {%0,%1,%2,%3};"
        : "+f"(d[0]), "+f"(d[1]), "+f"(d[2]), "+f"(d[3])
        : "r"(a[0]), "r"(a[1]), "r"(a[2]), "r"(a[3]), "r"(b[0]), "r"(b[1]));
}

// ---------------------------------------------------------------------------
// fp16 tensor-core GEMM: C = scale * A * B^T (+bias over cols)
//   A: [M][>=Kd] fp16, row stride ldA; B: [N][>=Kd] fp16, row stride ldB.
//   Kd = K extent actually multiplied (multiple of 64; may be < row stride,
//   used to skip known-zero trailing K, e.g. padded softmax columns).
//   CTA tile 128x128, warp tile 64x32 (8 warps 2x4), K-chunk 64,
//   3-stage cp.async ring, fp32 accum in mma.
//   MODE 0: fp32 out; MODE 1: fp16 out; MODE 2: fp16 TRANSPOSED out.
//   Batched via blockIdx.z (element strides sA, sB, sC).
// ---------------------------------------------------------------------------
#define STAGE_B 32768            // A tile 16KB + B tile 16KB
#define TG_SMEM (3 * STAGE_B)    // 98304 bytes

__device__ __forceinline__ void fill_chunk(uint32_t sm,
    const __half* A, const __half* Bm, int ldA, int ldB, int t, int c)
{
    long long k0 = (long long)c << 6;
#pragma unroll
    for (int i = 0; i < 4; i++) {
        int seg = t + (i << 8);          // 0..1023 = row*8 + chunk
        int row = seg >> 3;
        int cc  = seg & 7;
        uint32_t so = swz(row, cc);
        asm volatile("cp.async.cg.shared.global [%0], [%1], 16;"
                     :: "r"(sm + so),
                        "l"(A + (long long)row * ldA + k0 + ((long long)cc << 3)));
        asm volatile("cp.async.cg.shared.global [%0], [%1], 16;"
                     :: "r"(sm + 16384u + so),
                        "l"(Bm + (long long)row * ldB + k0 + ((long long)cc << 3)));
    }
}

template <int MODE, bool BIAS>
__global__ void __launch_bounds__(256, 2)
tgemm(const __half* __restrict__ A, const __half* __restrict__ Bm,
      float* __restrict__ Cf, __half* __restrict__ Ch,
      const float* __restrict__ bias,
      int Kd, int ldA, int ldB, int ldc, float scale,
      long long sA, long long sB, long long sC)
{
    extern __shared__ __align__(1024) char smem[];
    const int tid = threadIdx.x, wid = tid >> 5, lane = tid & 31;
    const long long z = blockIdx.z;
    A += z * sA; Bm += z * sB;
    if (MODE == 0) Cf += z * sC; else Ch += z * sC;

    const uint32_t sb = smem_u32(smem);
    const __half* At = A  + (long long)blockIdx.y * 128 * ldA;
    const __half* Bt = Bm + (long long)blockIdx.x * 128 * ldB;

    const int wr = wid >> 2, wc = wid & 3;    // 2 x 4 warp grid
    const int m0 = wr * 64, n0 = wc * 32;

    float acc[4][4][4];
#pragma unroll
    for (int i = 0; i < 4; i++)
#pragma unroll
        for (int j = 0; j < 4; j++)
#pragma unroll
            for (int r = 0; r < 4; r++) acc[i][j][r] = 0.f;

    const int NC = Kd >> 6;
    fill_chunk(sb, At, Bt, ldA, ldB, tid, 0);
    asm volatile("cp.async.commit_group;");
    if (NC > 1) {
        fill_chunk(sb + STAGE_B, At, Bt, ldA, ldB, tid, 1);
        asm volatile("cp.async.commit_group;");
    }

#pragma unroll 1
    for (int c = 0; c < NC; c++) {
        if (c == NC - 1) asm volatile("cp.async.wait_group 0;");
        else             asm volatile("cp.async.wait_group 1;");
        __syncthreads();

        const uint32_t tb = sb + (uint32_t)(c % 3) * STAGE_B;
        const uint32_t aA = tb, aB = tb + 16384u;

#pragma unroll
        for (int kk = 0; kk < 4; kk++) {
            const int k16 = kk << 1;  // 16B-chunk base of this 16-K step
            uint32_t Af[4][4], Bf[2][4];
            const int ar = m0 + (lane & 15);
            const int ac = k16 + (lane >> 4);
#pragma unroll
            for (int i = 0; i < 4; i++)
                ldsm4(Af[i], aA + swz(ar + 16 * i, ac));
            const int br = n0 + ((lane >> 4) << 3) + (lane & 7);
            const int bc = k16 + ((lane >> 3) & 1);
#pragma unroll
            for (int j2 = 0; j2 < 2; j2++)
                ldsm4(Bf[j2], aB + swz(br + 16 * j2, bc));
#pragma unroll
            for (int i = 0; i < 4; i++)
#pragma unroll
                for (int jt = 0; jt < 4; jt++)
                    mma_f16(acc[i][jt], Af[i], &Bf[jt >> 1][(jt & 1) << 1]);
        }
        if (c + 2 < NC) {
            fill_chunk(sb + (uint32_t)((c + 2) % 3) * STAGE_B, At, Bt, ldA, ldB,
                       tid, c + 2);
            asm volatile("cp.async.commit_group;");
        }
    }

    // ---------------- epilogue ----------------
    const int row0 = blockIdx.y * 128, col0 = blockIdx.x * 128;
    const int rl = lane >> 2;              // 0..7
    const int cl = (lane & 3) << 1;        // 0,2,4,6
#pragma unroll
    for (int i = 0; i < 4; i++) {
        const long long rg0 = row0 + m0 + i * 16 + rl;
        const long long rg1 = rg0 + 8;
#pragma unroll
        for (int j = 0; j < 4; j++) {
            const int cg = col0 + n0 + j * 8 + cl;
            float v00 = acc[i][j][0] * scale, v01 = acc[i][j][1] * scale;
            float v10 = acc[i][j][2] * scale, v11 = acc[i][j][3] * scale;
            if (BIAS) {
                const float b0 = bias[cg], b1 = bias[cg + 1];
                v00 += b0; v01 += b1; v10 += b0; v11 += b1;
            }
            if (MODE == 0) {
                *(float2*)(Cf + rg0 * ldc + cg) = make_float2(v00, v01);
                *(float2*)(Cf + rg1 * ldc + cg) = make_float2(v10, v11);
            } else if (MODE == 1) {
                *(__half2*)(Ch + rg0 * ldc + cg) =
                    __halves2half2(__float2half_rn(v00), __float2half_rn(v01));
                *(__half2*)(Ch + rg1 * ldc + cg) =
                    __halves2half2(__float2half_rn(v10), __float2half_rn(v11));
            } else {
                Ch[(long long)cg * ldc + rg0]       = __float2half_rn(v00);
                Ch[(long long)(cg + 1) * ldc + rg0] = __float2half_rn(v01);
                Ch[(long long)cg * ldc + rg1]       = __float2half_rn(v10);
                Ch[(long long)(cg + 1) * ldc + rg1] = __float2half_rn(v11);
            }
        }
    }
}

// ---------------------------------------------------------------------------
// Register-cached row softmax: ONE read of S, one exp, one fp16 write.
// Row length npad <= 2176 -> <=544 float4 -> <=3 per thread at 256 threads.
// Pad keys (>= n) written as 0.
// ---------------------------------------------------------------------------
__global__ void softmax_reg(const float* __restrict__ S, __half* __restrict__ P,
                            int n, int npad)
{
    const long long roff = ((long long)blockIdx.y * npad + blockIdx.x) * npad;
    const float4* row4 = (const float4*)(S + roff);
    __half* pr = P + roff;
    const int t = threadIdx.x;
    const int npad4 = npad >> 2;
    __shared__ float red[256];

    float4 v[3];
    float m = -1e30f;
#pragma unroll
    for (int p = 0; p < 3; p++) {
        const int i4 = t + (p << 8);
        if (i4 < npad4) {
            v[p] = row4[i4];
            const int j = i4 << 2;
            if (j + 0 < n) m = fmaxf(m, v[p].x);
            if (j + 1 < n) m = fmaxf(m, v[p].y);
            if (j + 2 < n) m = fmaxf(m, v[p].z);
            if (j + 3 < n) m = fmaxf(m, v[p].w);
        }
    }
    red[t] = m; __syncthreads();
    for (int s = 128; s > 0; s >>= 1) {
        if (t < s) red[t] = fmaxf(red[t], red[t + s]);
        __syncthreads();
    }
    m = red[0]; __syncthreads();

    float sum = 0.f;
#pragma unroll
    for (int p = 0; p < 3; p++) {
        const int i4 = t + (p << 8);
        if (i4 < npad4) {
            const int j = i4 << 2;
            v[p].x = (j + 0 < n) ? __expf(v[p].x - m) : 0.f;
            v[p].y = (j + 1 < n) ? __expf(v[p].y - m) : 0.f;
            v[p].z = (j + 2 < n) ? __expf(v[p].z - m) : 0.f;
            v[p].w = (j + 3 < n) ? __expf(v[p].w - m) : 0.f;
            sum += v[p].x + v[p].y + v[p].z + v[p].w;
        }
    }
    red[t] = sum; __syncthreads();
    for (int s = 128; s > 0; s >>= 1) {
        if (t < s) red[t] += red[t + s];
        __syncthreads();
    }
    const float inv = 1.f / red[0];

#pragma unroll
    for (int p = 0; p < 3; p++) {
        const int i4 = t + (p << 8);
        if (i4 < npad4) {
            const int j = i4 << 2;
            *(__half2*)(pr + j)     = __halves2half2(__float2half_rn(v[p].x * inv),
                                                     __float2half_rn(v[p].y * inv));
            *(__half2*)(pr + j + 2) = __halves2half2(__float2half_rn(v[p].z * inv),
                                                     __float2half_rn(v[p].w * inv));
        }
    }
}

// ---------------------------------------------------------------------------
// Input assembly (fp32 -> fp16), 2 elems/thread (half2 stores)
// ---------------------------------------------------------------------------
__global__ void build_x0h(const float* __restrict__ seg0, __half* __restrict__ X)
{
    int b = blockIdx.y;
    long long i2 = (long long)blockIdx.x * 256 + threadIdx.x;   // over NP*Dn/2
    int pos = (int)(i2 >> 9), d = (int)((i2 & 511) << 1);
    float2 v = make_float2(0.f, 0.f);
    if (pos >= 1 && pos <= 2048)
        v = *(const float2*)(seg0 + ((long long)b * 2048 + (pos - 1)) * 1024 + d);
    *(__half2*)(X + (long long)b * NP * 1024 + (i2 << 1)) =
        __halves2half2(__float2half_rn(v.x), __float2half_rn(v.y));
}

__global__ void build_xsh(const float* __restrict__ seg1, const float* __restrict__ pe,
                          __half* __restrict__ X)
{
    int b = blockIdx.y;
    long long i2 = (long long)blockIdx.x * 256 + threadIdx.x;   // over NS*Dn/2
    int pos = (int)(i2 >> 9), d = (int)((i2 & 511) << 1);
    float2 v = make_float2(0.f, 0.f);
    if (pos == 0 || pos == 513) v = *(const float2*)(pe + d);
    else if (pos >= 1 && pos <= 512)
        v = *(const float2*)(seg1 + ((long long)b * 2048 + (pos - 1)) * 1024 + d);
    *(__half2*)(X + (long long)b * NS * 1024 + (i2 << 1)) =
        __halves2half2(__float2half_rn(v.x), __float2half_rn(v.y));
}

__global__ void build_x1h(const float* __restrict__ seg0, const float* __restrict__ seg1,
                          const float* __restrict__ P1, __half* __restrict__ X)
{
    int b = blockIdx.y;
    long long i2 = (long long)blockIdx.x * 256 + threadIdx.x;   // over NP*Dn/2
    int pos = (int)(i2 >> 9), d = (int)((i2 & 511) << 1);
    float2 v = make_float2(0.f, 0.f);
    if (pos < 32)
        v = *(const float2*)(seg0 + ((long long)b * 2048 + (2016 + pos)) * 1024 + d);
    else if (pos == 32 || pos == 2081)
        v = *(const float2*)(P1 + b * 1024 + d);
    else if (pos >= 33 && pos <= 2080)
        v = *(const float2*)(seg1 + ((long long)b * 2048 + (pos - 33)) * 1024 + d);
    *(__half2*)(X + (long long)b * NP * 1024 + (i2 << 1)) =
        __halves2half2(__float2half_rn(v.x), __float2half_rn(v.y));
}

// smem-tiled weight transpose + convert: WT[n][k] = half(W[k][n])
__global__ void wcvt_t(const float* __restrict__ W, __half* __restrict__ WT)
{
    __shared__ float tile[32][33];
    const int k0 = blockIdx.y * 32, n0 = blockIdx.x * 32;
    for (int r = threadIdx.y; r < 32; r += 8)
        tile[r][threadIdx.x] = W[(long long)(k0 + r) * 1024 + n0 + threadIdx.x];
    __syncthreads();
    for (int r = threadIdx.y; r < 32; r += 8)
        WT[(long long)(n0 + r) * 1024 + k0 + threadIdx.x] =
            __float2half_rn(tile[threadIdx.x][r]);
}

// copy tokens [33, 33+tokens) of H (stride npad) into output region, float4
__global__ void copy_out(const float* __restrict__ H, float* __restrict__ out,
                         int tokens, int npad, long long off)
{
    int b = blockIdx.y;
    long long i4 = (long long)blockIdx.x * 256 + threadIdx.x;  // over tokens*1024/4
    *(float4*)(out + off + (long long)b * tokens * 1024 + (i4 << 2)) =
        *(const float4*)(H + (long long)b * npad * 1024 + 33LL * 1024 + (i4 << 2));
}

__global__ void copy_pad128(const float* __restrict__ H, float* __restrict__ dst,
                            int npad, int token)
{
    long long i = (long long)blockIdx.x * 256 + threadIdx.x;
    int r = (int)(i >> 10), d = (int)(i & 1023);
    dst[i] = (r < Bn) ? H[((long long)r * npad + token) * 1024 + d] : 0.f;
}

// ---------------------------------------------------------------------------
// fp32 fallback SGEMM (stage C only; tiny)
// ---------------------------------------------------------------------------
template <bool TRANSB, bool BIAS>
__global__ void __launch_bounds__(256)
sgemm(const float* __restrict__ A, const float* __restrict__ Bm,
      float* __restrict__ C, const float* __restrict__ bias,
      int N, int Kd, float scale)
{
    __shared__ float As[8][128];
    __shared__ float Bs[8][128];
    const int t = threadIdx.x, tx = t & 15, ty = t >> 4;
    const int row0 = blockIdx.y * 128, col0 = blockIdx.x * 128;
    const int aRow = t >> 1, aCol = (t & 1) << 2;
    const int bRow = t >> 5, bCol = (t & 31) << 2;
    float acc[8][8];
#pragma unroll
    for (int i = 0; i < 8; i++)
#pragma unroll
        for (int j = 0; j < 8; j++) acc[i][j] = 0.f;
    const float* Aptr = A + (long long)(row0 + aRow) * Kd + aCol;
    const float* Bptr = TRANSB ? (Bm + (long long)(col0 + aRow) * Kd + aCol)
                               : (Bm + (long long)bRow * N + col0 + bCol);
    for (int k0 = 0; k0 < Kd; k0 += 8) {
        float4 av = *(const float4*)(Aptr + k0);
        As[aCol + 0][aRow] = av.x; As[aCol + 1][aRow] = av.y;
        As[aCol + 2][aRow] = av.z; As[aCol + 3][aRow] = av.w;
        if (TRANSB) {
            float4 bv = *(const float4*)(Bptr + k0);
            Bs[aCol + 0][aRow] = bv.x; Bs[aCol + 1][aRow] = bv.y;
            Bs[aCol + 2][aRow] = bv.z; Bs[aCol + 3][aRow] = bv.w;
        } else {
            float4 bv = *(const float4*)(Bptr + (long long)k0 * N);
            *(float4*)&Bs[bRow][bCol] = bv;
        }
        __syncthreads();
#pragma unroll
        for (int kk = 0; kk < 8; kk++) {
            float ar[8], br[8];
            *(float4*)&ar[0] = *(const float4*)&As[kk][ty * 8];
            *(float4*)&ar[4] = *(const float4*)&As[kk][ty * 8 + 4];
            *(float4*)&br[0] = *(const float4*)&Bs[kk][tx * 8];
            *(float4*)&br[4] = *(const float4*)&Bs[kk][tx * 8 + 4];
#pragma unroll
            for (int i = 0; i < 8; i++)
#pragma unroll
                for (int j = 0; j < 8; j++)
                    acc[i][j] = fmaf(ar[i], br[j], acc[i][j]);
        }
        __syncthreads();
    }
#pragma unroll
    for (int i = 0; i < 8; i++) {
        long long r = row0 + ty * 8 + i;
#pragma unroll
        for (int j = 0; j < 8; j += 4) {
            int c = col0 + tx * 8 + j;
            float4 v;
            v.x = acc[i][j + 0] * scale; v.y = acc[i][j + 1] * scale;
            v.z = acc[i][j + 2] * scale; v.w = acc[i][j + 3] * scale;
            if (BIAS) { v.x += bias[c]; v.y += bias[c + 1]; v.z += bias[c + 2]; v.w += bias[c + 3]; }
            *(float4*)(C + r * N + c) = v;
        }
    }
}

// Tiny 8-way memory attention
__global__ void mem_attn(const float* __restrict__ Qn, const float* __restrict__ Kp,
                         const float* __restrict__ M1, float* __restrict__ P1)
{
    int b = blockIdx.x, t = threadIdx.x;
    __shared__ float red[256];
    __shared__ float attn[Bn];
    for (int j = 0; j < Bn; j++) {
        float p = 0.f;
        for (int d = t; d < 1024; d += 256)
            p += Qn[b * 1024 + d] * Kp[j * 1024 + d];
        red[t] = p; __syncthreads();
        for (int s = 128; s > 0; s >>= 1) {
            if (t < s) red[t] += red[t + s];
            __syncthreads();
        }
        if (t == 0) attn[j] = red[0] * 0.03125f;
        __syncthreads();
    }
    if (t == 0) {
        float m = -1e30f;
        for (int j = 0; j < Bn; j++) m = fmaxf(m, attn[j]);
        float s = 0.f;
        for (int j = 0; j < Bn; j++) { attn[j] = __expf(attn[j] - m); s += attn[j]; }
        float inv = 1.f / s;
        for (int j = 0; j < Bn; j++) attn[j] *= inv;
    }
    __syncthreads();
    for (int d = t; d < 1024; d += 256) {
        float v = 0.f;
#pragma unroll
        for (int j = 0; j < Bn; j++) v += attn[j] * M1[j * 1024 + d];
        P1[b * 1024 + d] = v;
    }
}

// ---------------------------------------------------------------------------
// Host orchestration
// ---------------------------------------------------------------------------
struct Ptrs {
    __half *X, *Q, *K, *Vt, *O, *P;
    __half *WqT, *WkT, *WvT, *WoT;
    float *S, *H, *M1, *S1, *Qn, *Kp, *P1;
};

static void run_backbone_tc(const Ptrs& p,
                            const float* bq, const float* bk,
                            const float* bv, const float* bo,
                            int n, int npad)
{
    const int mt = npad / 128;
    const long long sXD = (long long)npad * Dn;
    const long long sPP = (long long)npad * npad;
    const int KT = ((n + 63) / 64) * 64;   // PV K-extent (P cols >= n are zero)
    dim3 gp(Dn / 128, mt, Bn);
    // projections
    tgemm<1, true><<<gp, 256, TG_SMEM>>>(p.X, p.WqT, nullptr, p.Q, bq,
                                         Dn, Dn, Dn, Dn, 1.f, sXD, 0, sXD);
    tgemm<1, true><<<gp, 256, TG_SMEM>>>(p.X, p.WkT, nullptr, p.K, bk,
                                         Dn, Dn, Dn, Dn, 1.f, sXD, 0, sXD);
    tgemm<2, true><<<gp, 256, TG_SMEM>>>(p.X, p.WvT, nullptr, p.Vt, bv,
                                         Dn, Dn, Dn, npad, 1.f, sXD, 0, sXD);
    // scores
    dim3 gs(mt, mt, Bn);
    tgemm<0, false><<<gs, 256, TG_SMEM>>>(p.Q, p.K, p.S, nullptr, nullptr,
                                          Dn, Dn, Dn, npad, 0.03125f,
                                          sXD, sXD, sPP);
    softmax_reg<<<dim3(n, Bn), 256>>>(p.S, p.P, n, npad);
    // attn @ V  (K-extent truncated to KT)
    tgemm<1, false><<<gp, 256, TG_SMEM>>>(p.P, p.Vt, nullptr, p.O, nullptr,
                                          KT, npad, npad, Dn, 1.f,
                                          sPP, sXD, sXD);
    // output proj
    tgemm<0, true><<<gp, 256, TG_SMEM>>>(p.O, p.WoT, p.H, nullptr, bo,
                                         Dn, Dn, Dn, Dn, 1.f, sXD, 0, sXD);
}

extern "C" void kernel_launch(void* const* d_in, const int* in_sizes, int n_in,
                              void* d_out, int out_size)
{
    const float* seg0   = (const float*)d_in[0];
    const float* seg1   = (const float*)d_in[1];
    const float* pe     = (const float*)d_in[2];
    const float* Wq_mem = (const float*)d_in[3];
    const float* bq_mem = (const float*)d_in[4];
    const float* Wk_mem = (const float*)d_in[5];
    const float* bk_mem = (const float*)d_in[6];
    const float* Wq     = (const float*)d_in[7];
    const float* bq     = (const float*)d_in[8];
    const float* Wk     = (const float*)d_in[9];
    const float* bk     = (const float*)d_in[10];
    const float* Wv     = (const float*)d_in[11];
    const float* bv     = (const float*)d_in[12];
    const float* Wo     = (const float*)d_in[13];
    const float* bo     = (const float*)d_in[14];
    float* out = (float*)d_out;

    cudaFuncSetAttribute(tgemm<0, false>, cudaFuncAttributeMaxDynamicSharedMemorySize, TG_SMEM);
    cudaFuncSetAttribute(tgemm<0, true>,  cudaFuncAttributeMaxDynamicSharedMemorySize, TG_SMEM);
    cudaFuncSetAttribute(tgemm<1, false>, cudaFuncAttributeMaxDynamicSharedMemorySize, TG_SMEM);
    cudaFuncSetAttribute(tgemm<1, true>,  cudaFuncAttributeMaxDynamicSharedMemorySize, TG_SMEM);
    cudaFuncSetAttribute(tgemm<2, true>,  cudaFuncAttributeMaxDynamicSharedMemorySize, TG_SMEM);

    Ptrs p;
    cudaGetSymbolAddress((void**)&p.X, g_X);
    cudaGetSymbolAddress((void**)&p.Q, g_Q);
    cudaGetSymbolAddress((void**)&p.K, g_K);
    cudaGetSymbolAddress((void**)&p.Vt, g_Vt);
    cudaGetSymbolAddress((void**)&p.O, g_O);
    cudaGetSymbolAddress((void**)&p.P, g_P);
    cudaGetSymbolAddress((void**)&p.WqT, g_WqT);
    cudaGetSymbolAddress((void**)&p.WkT, g_WkT);
    cudaGetSymbolAddress((void**)&p.WvT, g_WvT);
    cudaGetSymbolAddress((void**)&p.WoT, g_WoT);
    cudaGetSymbolAddress((void**)&p.S, g_S);
    cudaGetSymbolAddress((void**)&p.H, g_H);
    cudaGetSymbolAddress((void**)&p.M1, g_M1);
    cudaGetSymbolAddress((void**)&p.S1, g_S1);
    cudaGetSymbolAddress((void**)&p.Qn, g_Qn);
    cudaGetSymbolAddress((void**)&p.Kp, g_Kp);
    cudaGetSymbolAddress((void**)&p.P1, g_P1);

    dim3 wg(32, 32), wb(32, 8);
    wcvt_t<<<wg, wb>>>(Wq, p.WqT);
    wcvt_t<<<wg, wb>>>(Wk, p.WkT);
    wcvt_t<<<wg, wb>>>(Wv, p.WvT);
    wcvt_t<<<wg, wb>>>(Wo, p.WoT);

    // ---- Stage A: backbone over input_h0 (n = 2050) ----
    build_x0h<<<dim3(NP * Dn / 512, Bn), 256>>>(seg0, p.X);
    run_backbone_tc(p, bq, bk, bv, bo, 2050, NP);
    copy_out<<<dim3(2016 * Dn / 1024, Bn), 256>>>(p.H, out, 2016, NP, 0LL);
    copy_pad128<<<dim3(128 * Dn / 256), 256>>>(p.H, p.M1, NP, 2049);

    // ---- Stage B: summarize(seg1) (n = 514) ----
    build_xsh<<<dim3(NS * Dn / 512, Bn), 256>>>(seg1, pe, p.X);
    run_backbone_tc(p, bq, bk, bv, bo, 514, NS);
    copy_pad128<<<dim3(128 * Dn / 256), 256>>>(p.H, p.S1, NS, 512);

    // ---- Stage C: memory attention (tiny, fp32 path) ----
    dim3 gMem(Dn / 128, 1, 1);
    sgemm<false, true><<<gMem, 256>>>(p.S1, Wq_mem, p.Qn, bq_mem, Dn, Dn, 1.f);
    sgemm<false, true><<<gMem, 256>>>(p.M1, Wk_mem, p.Kp, bk_mem, Dn, Dn, 1.f);
    mem_attn<<<Bn, 256>>>(p.Qn, p.Kp, p.M1, p.P1);

    // ---- Stage D: backbone over input_h1 (n = 2082) ----
    build_x1h<<<dim3(NP * Dn / 512, Bn), 256>>>(seg0, seg1, p.P1, p.X);
    run_backbone_tc(p, bq, bk, bv, bo, 2082, NP);
    copy_out<<<dim3(2048 * Dn / 1024, Bn), 256>>>(p.H, out, 2048, NP,
                                                  (long long)Bn * 2016 * Dn);
}